// round 14
// baseline (speedup 1.0000x reference)
#include <cuda_runtime.h>
#include <cuda_fp16.h>
#include <cstdint>
#include <math.h>

#define BB 2
#define SS 4096
#define EE 1024
#define HH 16
#define DD 64
#define WW 256

#define NTOT 3072
#define NCHUNK 16

typedef unsigned long long u64;

// ---------------- scratch (__device__ globals, no allocs) -------------------
__device__ __align__(16) __half g_Qb[BB * HH * SS * DD];  // [B,H,S,D] fp16
__device__ __align__(16) __half g_Kb[BB * HH * SS * DD];  // [B,H,S,D] fp16
__device__ __align__(16) __half g_VT[BB * HH * DD * SS];  // [B,H,D,S] fp16
__device__ __align__(16) __half g_Xf[BB * SS * EE];       // fp16 hidden states
__device__ __align__(16) __half g_Wf[NTOT * EE];          // fp16 Q|K|V weights

// ---------------- PTX helpers ----------------------------------------------
__device__ __forceinline__ uint32_t smem_u32(const void* p) {
    uint32_t a;
    asm("{ .reg .u64 t; cvta.to.shared.u64 t, %1; cvt.u32.u64 %0, t; }" : "=r"(a) : "l"(p));
    return a;
}
#define SWZ(o) ((o) ^ (((o) >> 3) & 0x70))

__device__ __forceinline__ void cp16(uint32_t s, const void* g) {
    asm volatile("cp.async.cg.shared.global [%0], [%1], 16;" :: "r"(s), "l"(g));
}
#define CP_COMMIT() asm volatile("cp.async.commit_group;" ::: "memory")
#define CP_WAIT1()  asm volatile("cp.async.wait_group 1;" ::: "memory")

__device__ __forceinline__ void ldsm4(uint32_t* r, uint32_t addr) {
    asm volatile("ldmatrix.sync.aligned.m8n8.x4.shared.b16 {%0,%1,%2,%3}, [%4];"
                 : "=r"(r[0]), "=r"(r[1]), "=r"(r[2]), "=r"(r[3]) : "r"(addr));
}
__device__ __forceinline__ void mma16816h(float* c, const uint32_t* a, uint32_t b0, uint32_t b1) {
    asm volatile("mma.sync.aligned.m16n8k16.row.col.f32.f16.f16.f32 "
                 "{%0,%1,%2,%3}, {%4,%5,%6,%7}, {%8,%9}, {%0,%1,%2,%3};"
                 : "+f"(c[0]), "+f"(c[1]), "+f"(c[2]), "+f"(c[3])
                 : "r"(a[0]), "r"(a[1]), "r"(a[2]), "r"(a[3]), "r"(b0), "r"(b1));
}
__device__ __forceinline__ uint32_t packh2(float lo, float hi) {
    uint32_t r;
    asm("cvt.rn.f16x2.f32 %0, %1, %2;" : "=r"(r) : "f"(hi), "f"(lo));
    return r;
}

// ---------------- fused fp32 -> fp16 convert --------------------------------
#define XELEM (BB * SS * EE)

__global__ void __launch_bounds__(256) conv_all(const float* __restrict__ X,
                                                const float* __restrict__ qw,
                                                const float* __restrict__ kw,
                                                const float* __restrict__ vw) {
    size_t i = ((size_t)blockIdx.x * 256 + threadIdx.x) * 4;
    if (i < XELEM) {
        float4 v = *(const float4*)(X + i);
        uint2 pk;
        pk.x = packh2(v.x, v.y);
        pk.y = packh2(v.z, v.w);
        *(uint2*)&g_Xf[i] = pk;
    } else {
        size_t j = i - XELEM;
        int proj = (int)(j >> 20);
        const float* W = (proj == 0) ? qw : (proj == 1) ? kw : vw;
        size_t loc = j & ((1u << 20) - 1);
        float4 v = *(const float4*)(W + loc);
        uint2 pk;
        pk.x = packh2(v.x, v.y);
        pk.y = packh2(v.z, v.w);
        *(uint2*)&g_Wf[j] = pk;
    }
}

// ---------------- HMMA QKV GEMM (4 warps, 64x64, 3-stage, 1 barrier/iter) ---
#define GEMM_SMEM 98304

__device__ __forceinline__ void issue_loads(uint32_t sb, int stage, int chunk,
                                            int m0, int n0, int tid) {
    const int kc = chunk * 64;
    const uint32_t Ab = sb + stage * 32768;
    const uint32_t Bb = Ab + 16384;
#pragma unroll
    for (int i = 0; i < 8; i++) {
        int u = tid + i * 128;
        int r = u >> 3, p = u & 7;
        cp16(Ab + SWZ(r * 128 + p * 16), (const void*)(g_Xf + (size_t)(m0 + r) * EE + kc + p * 8));
    }
#pragma unroll
    for (int i = 0; i < 8; i++) {
        int u = tid + i * 128;
        int r = u >> 3, p = u & 7;
        cp16(Bb + SWZ(r * 128 + p * 16), (const void*)(g_Wf + (size_t)(n0 + r) * EE + kc + p * 8));
    }
}

__global__ void __launch_bounds__(128) qkv_hmma_gemm(const float* __restrict__ qb,
                                                     const float* __restrict__ kb,
                                                     const float* __restrict__ vb) {
    extern __shared__ char smraw[];
    const uint32_t sb = smem_u32(smraw);
    const int tid = threadIdx.x;
    const int wid = tid >> 5;
    const int lane = tid & 31;
    const int n0 = blockIdx.x * 128;
    const int m0 = blockIdx.y * 128;

    const int warpRow = (wid & 1) * 64;
    const int warpCol = (wid >> 1) * 64;
    const int lrow = lane & 15;
    const int lsel = (lane >> 4) * 16;

    float acc[4][8][4];
#pragma unroll
    for (int mi = 0; mi < 4; mi++)
#pragma unroll
        for (int ni = 0; ni < 8; ni++)
#pragma unroll
            for (int r = 0; r < 4; r++) acc[mi][ni][r] = 0.f;

    issue_loads(sb, 0, 0, m0, n0, tid); CP_COMMIT();
    issue_loads(sb, 1, 1, m0, n0, tid); CP_COMMIT();

    for (int c = 0; c < NCHUNK; c++) {
        const int stage = c % 3;
        CP_WAIT1();
        __syncthreads();
        // Prefetch distance 2: chunk c+2 targets stage (c+2)%3 == (c-1)%3,
        // whose consumers all finished before the barrier above.
        if (c + 2 < NCHUNK) issue_loads(sb, (c + 2) % 3, c + 2, m0, n0, tid);
        CP_COMMIT();

        const uint32_t Ab = sb + stage * 32768;
        const uint32_t Bb = Ab + 16384;
#pragma unroll
        for (int kk = 0; kk < 4; kk++) {
            uint32_t afr[4][4];
#pragma unroll
            for (int mi = 0; mi < 4; mi++) {
                uint32_t o = (warpRow + mi * 16 + lrow) * 128 + kk * 32 + lsel;
                ldsm4(afr[mi], Ab + SWZ(o));
            }
            uint32_t bfr[4][4];
#pragma unroll
            for (int bi = 0; bi < 4; bi++) {
                uint32_t o = (warpCol + bi * 16 + lrow) * 128 + kk * 32 + lsel;
                ldsm4(bfr[bi], Bb + SWZ(o));
            }
#pragma unroll
            for (int mi = 0; mi < 4; mi++)
#pragma unroll
                for (int ni = 0; ni < 8; ni++)
                    mma16816h(acc[mi][ni], afr[mi],
                              bfr[ni >> 1][ni & 1], bfr[ni >> 1][(ni & 1) + 2]);
        }
    }
    __syncthreads();

    // -------- epilogue: stage C in smem, bias + fp16 + layout transform -----
    float* Cs = (float*)smraw;   // [128][132]
#pragma unroll
    for (int mi = 0; mi < 4; mi++)
#pragma unroll
        for (int ni = 0; ni < 8; ni++) {
            const int r = warpRow + mi * 16 + (lane >> 2);
            const int col = warpCol + ni * 8 + (lane & 3) * 2;
            Cs[r * 132 + col]       = acc[mi][ni][0];
            Cs[r * 132 + col + 1]   = acc[mi][ni][1];
            Cs[(r + 8) * 132 + col]     = acc[mi][ni][2];
            Cs[(r + 8) * 132 + col + 1] = acc[mi][ni][3];
        }
    __syncthreads();

    const int proj = n0 >> 10;
    const int nb1023 = n0 & 1023;
    const int h0 = nb1023 >> 6;
    const int b = m0 >> 12;
    const int s_base = m0 & (SS - 1);

    if (proj < 2) {
        __half* dst = (proj == 0) ? g_Qb : g_Kb;
        const float* bp = (proj == 0) ? qb : kb;
        const float scale = (proj == 0) ? 0.125f : 1.0f;
#pragma unroll
        for (int it = 0; it < 32; it++) {
            const int id = tid + it * 128;
            const int col = (id & 31) * 4;
            const int s = id >> 5;
            const int h = h0 + (col >> 6);
            const int d = col & 63;
            float v0 = (Cs[s * 132 + col]     + bp[nb1023 + col])     * scale;
            float v1 = (Cs[s * 132 + col + 1] + bp[nb1023 + col + 1]) * scale;
            float v2 = (Cs[s * 132 + col + 2] + bp[nb1023 + col + 2]) * scale;
            float v3 = (Cs[s * 132 + col + 3] + bp[nb1023 + col + 3]) * scale;
            uint2 pk;
            pk.x = packh2(v0, v1);
            pk.y = packh2(v2, v3);
            *(uint2*)&dst[((size_t)(b * HH + h) * SS + s_base + s) * DD + d] = pk;
        }
    } else {
#pragma unroll
        for (int it = 0; it < 32; it++) {
            const int id = tid + it * 128;
            const int col = id >> 5;
            const int s4 = (id & 31) * 4;
            const int h = h0 + (col >> 6);
            const int d = col & 63;
            const float bv = vb[nb1023 + col];
            float v0 = Cs[(s4 + 0) * 132 + col] + bv;
            float v1 = Cs[(s4 + 1) * 132 + col] + bv;
            float v2 = Cs[(s4 + 2) * 132 + col] + bv;
            float v3 = Cs[(s4 + 3) * 132 + col] + bv;
            uint2 pk;
            pk.x = packh2(v0, v1);
            pk.y = packh2(v2, v3);
            *(uint2*)&g_VT[((size_t)(b * HH + h) * DD + d) * SS + s_base + s4] = pk;
        }
    }
}

// ---------------- HMMA banded flash attention: 128 q/CTA, 3-stage ring ------
// SMEM: Qs 16KB @0; stage s (s=0..2): K 8KB @16384+s*16384, V @+8192;
// fms 640 floats @65536. Total 68096 B. 2 CTAs/SM.
#define ATT_SMEM 68096

__device__ __forceinline__ void att_issue(uint32_t sb, int stage, int t,
                                          int q0, int bh, int tid) {
    const int j0 = q0 - WW + t * 64;   // in [0, SS-64] for t in [kstart, ke]
    const uint32_t Kb = sb + 16384 + stage * 16384;
    const uint32_t Vb = Kb + 8192;
    const __half* Kg = g_Kb + (size_t)bh * SS * DD + (size_t)j0 * DD;
    const __half* Vg = g_VT + (size_t)bh * DD * SS + j0;
#pragma unroll
    for (int i = 0; i < 2; i++) {
        const int u = tid + i * 256;
        const int r = u >> 3, p = u & 7;
        cp16(Kb + SWZ(r * 128 + p * 16), (const void*)(Kg + (size_t)r * DD + p * 8));
        cp16(Vb + SWZ(r * 128 + p * 16), (const void*)(Vg + (size_t)r * SS + p * 8));
    }
}

__global__ void __launch_bounds__(256, 2) attn_hmma(const int* __restrict__ amask,
                                                    float* __restrict__ out) {
    extern __shared__ char smraw[];
    const uint32_t sb = smem_u32(smraw);
    float* fms = (float*)(smraw + 65536);

    const int tid = threadIdx.x;
    const int wid = tid >> 5;
    const int lane = tid & 31;
    const int qt = blockIdx.x & 31;
    const int h = (blockIdx.x >> 5) & 15;
    const int b = blockIdx.x >> 9;
    const int q0 = qt * 128;
    const int bh = b * HH + h;

    // Load Q tile: 128 rows x 128B, swizzled
    {
        const __half* Qg = g_Qb + (size_t)(bh * SS + q0) * DD;
#pragma unroll
        for (int i = 0; i < 4; i++) {
            const int u = tid + i * 256;
            const int r = u >> 3, p = u & 7;
            uint4 v = *(const uint4*)(Qg + r * DD + p * 8);
            *(uint4*)(smraw + SWZ(r * 128 + p * 16)) = v;
        }
    }
    // fms over key span [q0-256, q0+384)
    int localmask = 0;
    for (int c = tid; c < 640; c += 256) {
        const int j = q0 - WW + c;
        const int mv = (j >= 0 && j < SS) ? amask[b * SS + j] : 0;
        fms[c] = (mv != 0) ? -10000.f : 0.f;
        localmask |= mv;
    }

    const int kstart = (q0 < WW) ? ((WW - q0) >> 6) : 0;
    const int ke = min(9, (SS + 192 - q0) >> 6);

    att_issue(sb, 0, kstart, q0, bh, tid); CP_COMMIT();
    if (kstart + 1 <= ke) att_issue(sb, 1, kstart + 1, q0, bh, tid);
    CP_COMMIT();
    const int anymask = __syncthreads_or(localmask);

    // Q fragments (held for whole block)
    const int lrow = lane & 15;
    const int lsel = (lane >> 4) * 16;
    uint32_t qf[4][4];
#pragma unroll
    for (int kk = 0; kk < 4; kk++)
        ldsm4(qf[kk], sb + SWZ((wid * 16 + lrow) * 128 + kk * 32 + lsel));

    const int row0 = q0 + wid * 16 + (lane >> 2);
    const int row1 = row0 + 8;
    const int colb = (lane & 3) * 2;

    float l_[2] = {0.f, 0.f};
    float o[8][4];
#pragma unroll
    for (int dt = 0; dt < 8; dt++)
#pragma unroll
        for (int r = 0; r < 4; r++) o[dt][r] = 0.f;

    for (int t = kstart; t <= ke; t++) {
        const int si = (t - kstart) % 3;
        CP_WAIT1();
        __syncthreads();
        // Prefetch distance 2: t+2 targets stage (t-kstart+2)%3, fully
        // consumed before the barrier above.
        if (t + 2 <= ke) att_issue(sb, (t - kstart + 2) % 3, t + 2, q0, bh, tid);
        CP_COMMIT();

        const int j0 = q0 - WW + t * 64;
        const uint32_t Kb = sb + 16384 + si * 16384;
        const uint32_t Vb = Kb + 8192;

        const int t4 = 4 * t;
        const bool skip = (t4 >= wid + 33) || (t4 <= wid - 4);
        const bool needmask = (t4 >= wid + 29) || (t4 <= wid);

        if (!skip) {
            // ---- scores S = Q K^T ----
            float sf[8][4];
#pragma unroll
            for (int nt = 0; nt < 8; nt++)
#pragma unroll
                for (int r = 0; r < 4; r++) sf[nt][r] = 0.f;

#pragma unroll
            for (int kk = 0; kk < 4; kk++) {
                uint32_t bfr[4][4];
#pragma unroll
                for (int nn = 0; nn < 4; nn++)
                    ldsm4(bfr[nn], Kb + SWZ((nn * 16 + lrow) * 128 + kk * 32 + lsel));
#pragma unroll
                for (int nt = 0; nt < 8; nt++)
                    mma16816h(sf[nt], qf[kk],
                              bfr[nt >> 1][nt & 1], bfr[nt >> 1][(nt & 1) + 2]);
            }

            // ---- mask + exp (no max subtraction) ----
            const int fbase = t * 64;
            if (needmask) {
#pragma unroll
                for (int nt = 0; nt < 8; nt++) {
#pragma unroll
                    for (int e = 0; e < 2; e++) {
                        const int kl = nt * 8 + colb + e;
                        const int j = j0 + kl;
                        const float fmv = fms[fbase + kl];
                        const bool v0 = (j - row0 <= WW) && (row0 - j <= WW);
                        const bool v1 = (j - row1 <= WW) && (row1 - j <= WW);
                        sf[nt][e]     = v0 ? sf[nt][e] + fmv     : -INFINITY;
                        sf[nt][2 + e] = v1 ? sf[nt][2 + e] + fmv : -INFINITY;
                    }
                }
            } else if (anymask) {
#pragma unroll
                for (int nt = 0; nt < 8; nt++) {
                    const float fmv0 = fms[fbase + nt * 8 + colb];
                    const float fmv1 = fms[fbase + nt * 8 + colb + 1];
                    sf[nt][0] += fmv0; sf[nt][1] += fmv1;
                    sf[nt][2] += fmv0; sf[nt][3] += fmv1;
                }
            }
#pragma unroll
            for (int nt = 0; nt < 8; nt++) {
                sf[nt][0] = __expf(sf[nt][0]);
                sf[nt][1] = __expf(sf[nt][1]);
                sf[nt][2] = __expf(sf[nt][2]);
                sf[nt][3] = __expf(sf[nt][3]);
                l_[0] += sf[nt][0] + sf[nt][1];
                l_[1] += sf[nt][2] + sf[nt][3];
            }

            // ---- P fragments (fp16) ----
            uint32_t pf[4][4];
#pragma unroll
            for (int kc = 0; kc < 4; kc++) {
                pf[kc][0] = packh2(sf[2 * kc][0],     sf[2 * kc][1]);
                pf[kc][1] = packh2(sf[2 * kc][2],     sf[2 * kc][3]);
                pf[kc][2] = packh2(sf[2 * kc + 1][0], sf[2 * kc + 1][1]);
                pf[kc][3] = packh2(sf[2 * kc + 1][2], sf[2 * kc + 1][3]);
            }

            // ---- O += P V ----
#pragma unroll
            for (int kc = 0; kc < 4; kc++) {
                uint32_t vfr[4][4];
#pragma unroll
                for (int nn = 0; nn < 4; nn++)
                    ldsm4(vfr[nn], Vb + SWZ((nn * 16 + lrow) * 128 + kc * 32 + lsel));
#pragma unroll
                for (int dt = 0; dt < 8; dt++)
                    mma16816h(o[dt], pf[kc],
                              vfr[dt >> 1][dt & 1], vfr[dt >> 1][(dt & 1) + 2]);
            }
        }
    }

    // ---- single l reduction after the loop ----
    l_[0] += __shfl_xor_sync(0xffffffffu, l_[0], 1);
    l_[0] += __shfl_xor_sync(0xffffffffu, l_[0], 2);
    l_[1] += __shfl_xor_sync(0xffffffffu, l_[1], 1);
    l_[1] += __shfl_xor_sync(0xffffffffu, l_[1], 2);

    // ---- normalize + store ----
    const float inv0 = 1.f / l_[0];
    const float inv1 = 1.f / l_[1];
    const size_t base0 = ((size_t)b * SS + row0) * EE + h * 64;
    const size_t base1 = base0 + (size_t)8 * EE;
#pragma unroll
    for (int dt = 0; dt < 8; dt++) {
        const int d = dt * 8 + colb;
        float2 w0 = make_float2(o[dt][0] * inv0, o[dt][1] * inv0);
        float2 w1 = make_float2(o[dt][2] * inv1, o[dt][3] * inv1);
        *(float2*)&out[base0 + d] = w0;
        *(float2*)&out[base1 + d] = w1;
    }
}

// ---------------------------------------------------------------------------
extern "C" void kernel_launch(void* const* d_in, const int* in_sizes, int n_in,
                              void* d_out, int out_size) {
    const float* hs  = (const float*)d_in[0];
    const int*   am  = (const int*)d_in[1];
    const float* q_w = (const float*)d_in[2];
    const float* q_b = (const float*)d_in[3];
    const float* k_w = (const float*)d_in[4];
    const float* k_b = (const float*)d_in[5];
    const float* v_w = (const float*)d_in[6];
    const float* v_b = (const float*)d_in[7];
    float* out = (float*)d_out;

    cudaFuncSetAttribute(qkv_hmma_gemm, cudaFuncAttributeMaxDynamicSharedMemorySize,
                         GEMM_SMEM);
    cudaFuncSetAttribute(attn_hmma, cudaFuncAttributeMaxDynamicSharedMemorySize,
                         ATT_SMEM);

    conv_all<<<(XELEM + 3 * EE * EE) / 1024, 256>>>(hs, q_w, k_w, v_w);

    dim3 g(NTOT / 128, (BB * SS) / 128);   // (24, 64)
    qkv_hmma_gemm<<<g, 128, GEMM_SMEM>>>(q_b, k_b, v_b);

    attn_hmma<<<BB * HH * (SS / 128), 256, ATT_SMEM>>>(am, out);
}

// round 16
// speedup vs baseline: 1.0172x; 1.0172x over previous
#include <cuda_runtime.h>
#include <cuda_fp16.h>
#include <cstdint>
#include <math.h>

#define BB 2
#define SS 4096
#define EE 1024
#define HH 16
#define DD 64
#define WW 256

#define NTOT 3072
#define NCHUNK 16

typedef unsigned long long u64;

// ---------------- scratch (__device__ globals, no allocs) -------------------
__device__ __align__(16) __half g_Qb[BB * HH * SS * DD];  // [B,H,S,D] fp16
__device__ __align__(16) __half g_Kb[BB * HH * SS * DD];  // [B,H,S,D] fp16
__device__ __align__(16) __half g_VT[BB * HH * DD * SS];  // [B,H,D,S] fp16
__device__ __align__(16) __half g_Xf[BB * SS * EE];       // fp16 hidden states
__device__ __align__(16) __half g_Wf[NTOT * EE];          // fp16 Q|K|V weights

// ---------------- PTX helpers ----------------------------------------------
__device__ __forceinline__ uint32_t smem_u32(const void* p) {
    uint32_t a;
    asm("{ .reg .u64 t; cvta.to.shared.u64 t, %1; cvt.u32.u64 %0, t; }" : "=r"(a) : "l"(p));
    return a;
}
#define SWZ(o) ((o) ^ (((o) >> 3) & 0x70))

__device__ __forceinline__ void cp16(uint32_t s, const void* g) {
    asm volatile("cp.async.cg.shared.global [%0], [%1], 16;" :: "r"(s), "l"(g));
}
#define CP_COMMIT() asm volatile("cp.async.commit_group;" ::: "memory")
#define CP_WAIT1()  asm volatile("cp.async.wait_group 1;" ::: "memory")

__device__ __forceinline__ void ldsm4(uint32_t* r, uint32_t addr) {
    asm volatile("ldmatrix.sync.aligned.m8n8.x4.shared.b16 {%0,%1,%2,%3}, [%4];"
                 : "=r"(r[0]), "=r"(r[1]), "=r"(r[2]), "=r"(r[3]) : "r"(addr));
}
__device__ __forceinline__ void mma16816h(float* c, const uint32_t* a, uint32_t b0, uint32_t b1) {
    asm volatile("mma.sync.aligned.m16n8k16.row.col.f32.f16.f16.f32 "
                 "{%0,%1,%2,%3}, {%4,%5,%6,%7}, {%8,%9}, {%0,%1,%2,%3};"
                 : "+f"(c[0]), "+f"(c[1]), "+f"(c[2]), "+f"(c[3])
                 : "r"(a[0]), "r"(a[1]), "r"(a[2]), "r"(a[3]), "r"(b0), "r"(b1));
}
__device__ __forceinline__ uint32_t packh2(float lo, float hi) {
    uint32_t r;
    asm("cvt.rn.f16x2.f32 %0, %1, %2;" : "=r"(r) : "f"(hi), "f"(lo));
    return r;
}

// ---------------- fused fp32 -> fp16 convert --------------------------------
#define XELEM (BB * SS * EE)

__global__ void __launch_bounds__(256) conv_all(const float* __restrict__ X,
                                                const float* __restrict__ qw,
                                                const float* __restrict__ kw,
                                                const float* __restrict__ vw) {
    size_t i = ((size_t)blockIdx.x * 256 + threadIdx.x) * 4;
    if (i < XELEM) {
        float4 v = *(const float4*)(X + i);
        uint2 pk;
        pk.x = packh2(v.x, v.y);
        pk.y = packh2(v.z, v.w);
        *(uint2*)&g_Xf[i] = pk;
    } else {
        size_t j = i - XELEM;
        int proj = (int)(j >> 20);
        const float* W = (proj == 0) ? qw : (proj == 1) ? kw : vw;
        size_t loc = j & ((1u << 20) - 1);
        float4 v = *(const float4*)(W + loc);
        uint2 pk;
        pk.x = packh2(v.x, v.y);
        pk.y = packh2(v.z, v.w);
        *(uint2*)&g_Wf[j] = pk;
    }
}

// ---------------- HMMA QKV GEMM (4 warps, 64x64, 2-stage, 3 CTAs/SM) --------
#define GEMM_SMEM 67584

__device__ __forceinline__ void issue_loads(uint32_t sb, int stage, int chunk,
                                            int m0, int n0, int tid) {
    const int kc = chunk * 64;
    const uint32_t Ab = sb + stage * 32768;
    const uint32_t Bb = Ab + 16384;
#pragma unroll
    for (int i = 0; i < 8; i++) {
        int u = tid + i * 128;
        int r = u >> 3, p = u & 7;
        cp16(Ab + SWZ(r * 128 + p * 16), (const void*)(g_Xf + (size_t)(m0 + r) * EE + kc + p * 8));
    }
#pragma unroll
    for (int i = 0; i < 8; i++) {
        int u = tid + i * 128;
        int r = u >> 3, p = u & 7;
        cp16(Bb + SWZ(r * 128 + p * 16), (const void*)(g_Wf + (size_t)(n0 + r) * EE + kc + p * 8));
    }
}

__global__ void __launch_bounds__(128) qkv_hmma_gemm(const float* __restrict__ qb,
                                                     const float* __restrict__ kb,
                                                     const float* __restrict__ vb) {
    extern __shared__ char smraw[];
    const uint32_t sb = smem_u32(smraw);
    const int tid = threadIdx.x;
    const int wid = tid >> 5;
    const int lane = tid & 31;
    const int n0 = blockIdx.x * 128;
    const int m0 = blockIdx.y * 128;

    const int warpRow = (wid & 1) * 64;
    const int warpCol = (wid >> 1) * 64;
    const int lrow = lane & 15;
    const int lsel = (lane >> 4) * 16;

    float acc[4][8][4];
#pragma unroll
    for (int mi = 0; mi < 4; mi++)
#pragma unroll
        for (int ni = 0; ni < 8; ni++)
#pragma unroll
            for (int r = 0; r < 4; r++) acc[mi][ni][r] = 0.f;

    issue_loads(sb, 0, 0, m0, n0, tid); CP_COMMIT();
    issue_loads(sb, 1, 1, m0, n0, tid); CP_COMMIT();

    for (int c = 0; c < NCHUNK; c++) {
        const int s = c & 1;
        CP_WAIT1();
        __syncthreads();
        const uint32_t Ab = sb + s * 32768;
        const uint32_t Bb = Ab + 16384;
#pragma unroll
        for (int kk = 0; kk < 4; kk++) {
            uint32_t afr[4][4];
#pragma unroll
            for (int mi = 0; mi < 4; mi++) {
                uint32_t o = (warpRow + mi * 16 + lrow) * 128 + kk * 32 + lsel;
                ldsm4(afr[mi], Ab + SWZ(o));
            }
            uint32_t bfr[4][4];
#pragma unroll
            for (int bi = 0; bi < 4; bi++) {
                uint32_t o = (warpCol + bi * 16 + lrow) * 128 + kk * 32 + lsel;
                ldsm4(bfr[bi], Bb + SWZ(o));
            }
#pragma unroll
            for (int mi = 0; mi < 4; mi++)
#pragma unroll
                for (int ni = 0; ni < 8; ni++)
                    mma16816h(acc[mi][ni], afr[mi],
                              bfr[ni >> 1][ni & 1], bfr[ni >> 1][(ni & 1) + 2]);
        }
        __syncthreads();
        if (c + 2 < NCHUNK) issue_loads(sb, s, c + 2, m0, n0, tid);
        CP_COMMIT();
    }
    __syncthreads();

    // -------- epilogue: stage C in smem, bias + fp16 + layout transform -----
    float* Cs = (float*)smraw;   // [128][132]
#pragma unroll
    for (int mi = 0; mi < 4; mi++)
#pragma unroll
        for (int ni = 0; ni < 8; ni++) {
            const int r = warpRow + mi * 16 + (lane >> 2);
            const int col = warpCol + ni * 8 + (lane & 3) * 2;
            Cs[r * 132 + col]       = acc[mi][ni][0];
            Cs[r * 132 + col + 1]   = acc[mi][ni][1];
            Cs[(r + 8) * 132 + col]     = acc[mi][ni][2];
            Cs[(r + 8) * 132 + col + 1] = acc[mi][ni][3];
        }
    __syncthreads();

    const int proj = n0 >> 10;
    const int nb1023 = n0 & 1023;
    const int h0 = nb1023 >> 6;
    const int b = m0 >> 12;
    const int s_base = m0 & (SS - 1);

    if (proj < 2) {
        __half* dst = (proj == 0) ? g_Qb : g_Kb;
        const float* bp = (proj == 0) ? qb : kb;
        const float scale = (proj == 0) ? 0.125f : 1.0f;
#pragma unroll
        for (int it = 0; it < 32; it++) {
            const int id = tid + it * 128;
            const int col = (id & 31) * 4;
            const int s = id >> 5;
            const int h = h0 + (col >> 6);
            const int d = col & 63;
            float v0 = (Cs[s * 132 + col]     + bp[nb1023 + col])     * scale;
            float v1 = (Cs[s * 132 + col + 1] + bp[nb1023 + col + 1]) * scale;
            float v2 = (Cs[s * 132 + col + 2] + bp[nb1023 + col + 2]) * scale;
            float v3 = (Cs[s * 132 + col + 3] + bp[nb1023 + col + 3]) * scale;
            uint2 pk;
            pk.x = packh2(v0, v1);
            pk.y = packh2(v2, v3);
            *(uint2*)&dst[((size_t)(b * HH + h) * SS + s_base + s) * DD + d] = pk;
        }
    } else {
#pragma unroll
        for (int it = 0; it < 32; it++) {
            const int id = tid + it * 128;
            const int col = id >> 5;
            const int s4 = (id & 31) * 4;
            const int h = h0 + (col >> 6);
            const int d = col & 63;
            const float bv = vb[nb1023 + col];
            float v0 = Cs[(s4 + 0) * 132 + col] + bv;
            float v1 = Cs[(s4 + 1) * 132 + col] + bv;
            float v2 = Cs[(s4 + 2) * 132 + col] + bv;
            float v3 = Cs[(s4 + 3) * 132 + col] + bv;
            uint2 pk;
            pk.x = packh2(v0, v1);
            pk.y = packh2(v2, v3);
            *(uint2*)&g_VT[((size_t)(b * HH + h) * DD + d) * SS + s_base + s4] = pk;
        }
    }
}

// ---------------- HMMA banded flash attention: 128 queries/CTA --------------
// (exact R13 configuration — proven 247.9 us)
#define ATT_SMEM 51712

__device__ __forceinline__ void att_issue(uint32_t sb, int stage, int t,
                                          int q0, int bh, int tid) {
    const int j0 = q0 - WW + t * 64;   // in [0, SS-64] for t in [kstart, ke]
    const uint32_t Kb = sb + 16384 + stage * 16384;
    const uint32_t Vb = Kb + 8192;
    const __half* Kg = g_Kb + (size_t)bh * SS * DD + (size_t)j0 * DD;
    const __half* Vg = g_VT + (size_t)bh * DD * SS + j0;
#pragma unroll
    for (int i = 0; i < 2; i++) {
        const int u = tid + i * 256;
        const int r = u >> 3, p = u & 7;
        cp16(Kb + SWZ(r * 128 + p * 16), (const void*)(Kg + (size_t)r * DD + p * 8));
        cp16(Vb + SWZ(r * 128 + p * 16), (const void*)(Vg + (size_t)r * SS + p * 8));
    }
}

__global__ void __launch_bounds__(256, 2) attn_hmma(const int* __restrict__ amask,
                                                    float* __restrict__ out) {
    extern __shared__ char smraw[];
    const uint32_t sb = smem_u32(smraw);
    float* fms = (float*)(smraw + 49152);

    const int tid = threadIdx.x;
    const int wid = tid >> 5;
    const int lane = tid & 31;
    const int qt = blockIdx.x & 31;
    const int h = (blockIdx.x >> 5) & 15;
    const int b = blockIdx.x >> 9;
    const int q0 = qt * 128;
    const int bh = b * HH + h;

    // Load Q tile: 128 rows x 128B, swizzled
    {
        const __half* Qg = g_Qb + (size_t)(bh * SS + q0) * DD;
#pragma unroll
        for (int i = 0; i < 4; i++) {
            const int u = tid + i * 256;
            const int r = u >> 3, p = u & 7;
            uint4 v = *(const uint4*)(Qg + r * DD + p * 8);
            *(uint4*)(smraw + SWZ(r * 128 + p * 16)) = v;
        }
    }
    // fms over key span [q0-256, q0+384)
    int localmask = 0;
    for (int c = tid; c < 640; c += 256) {
        const int j = q0 - WW + c;
        const int mv = (j >= 0 && j < SS) ? amask[b * SS + j] : 0;
        fms[c] = (mv != 0) ? -10000.f : 0.f;
        localmask |= mv;
    }

    const int kstart = (q0 < WW) ? ((WW - q0) >> 6) : 0;
    const int ke = min(9, (SS + 192 - q0) >> 6);

    att_issue(sb, 0, kstart, q0, bh, tid); CP_COMMIT();
    if (kstart + 1 <= ke) att_issue(sb, 1, kstart + 1, q0, bh, tid);
    CP_COMMIT();
    const int anymask = __syncthreads_or(localmask);

    // Q fragments (held for whole block)
    const int lrow = lane & 15;
    const int lsel = (lane >> 4) * 16;
    uint32_t qf[4][4];
#pragma unroll
    for (int kk = 0; kk < 4; kk++)
        ldsm4(qf[kk], sb + SWZ((wid * 16 + lrow) * 128 + kk * 32 + lsel));

    const int row0 = q0 + wid * 16 + (lane >> 2);
    const int row1 = row0 + 8;
    const int colb = (lane & 3) * 2;

    float l_[2] = {0.f, 0.f};
    float o[8][4];
#pragma unroll
    for (int dt = 0; dt < 8; dt++)
#pragma unroll
        for (int r = 0; r < 4; r++) o[dt][r] = 0.f;

    for (int t = kstart; t <= ke; t++) {
        const int s = (t - kstart) & 1;
        CP_WAIT1();
        __syncthreads();
        const int j0 = q0 - WW + t * 64;
        const uint32_t Kb = sb + 16384 + s * 16384;
        const uint32_t Vb = Kb + 8192;

        const int t4 = 4 * t;
        const bool skip = (t4 >= wid + 33) || (t4 <= wid - 4);
        const bool needmask = (t4 >= wid + 29) || (t4 <= wid);

        if (!skip) {
            // ---- scores S = Q K^T ----
            float sf[8][4];
#pragma unroll
            for (int nt = 0; nt < 8; nt++)
#pragma unroll
                for (int r = 0; r < 4; r++) sf[nt][r] = 0.f;

#pragma unroll
            for (int kk = 0; kk < 4; kk++) {
                uint32_t bfr[4][4];
#pragma unroll
                for (int nn = 0; nn < 4; nn++)
                    ldsm4(bfr[nn], Kb + SWZ((nn * 16 + lrow) * 128 + kk * 32 + lsel));
#pragma unroll
                for (int nt = 0; nt < 8; nt++)
                    mma16816h(sf[nt], qf[kk],
                              bfr[nt >> 1][nt & 1], bfr[nt >> 1][(nt & 1) + 2]);
            }

            // ---- mask + exp (no max subtraction) ----
            const int fbase = t * 64;
            if (needmask) {
#pragma unroll
                for (int nt = 0; nt < 8; nt++) {
#pragma unroll
                    for (int e = 0; e < 2; e++) {
                        const int kl = nt * 8 + colb + e;
                        const int j = j0 + kl;
                        const float fmv = fms[fbase + kl];
                        const bool v0 = (j - row0 <= WW) && (row0 - j <= WW);
                        const bool v1 = (j - row1 <= WW) && (row1 - j <= WW);
                        sf[nt][e]     = v0 ? sf[nt][e] + fmv     : -INFINITY;
                        sf[nt][2 + e] = v1 ? sf[nt][2 + e] + fmv : -INFINITY;
                    }
                }
            } else if (anymask) {
#pragma unroll
                for (int nt = 0; nt < 8; nt++) {
                    const float fmv0 = fms[fbase + nt * 8 + colb];
                    const float fmv1 = fms[fbase + nt * 8 + colb + 1];
                    sf[nt][0] += fmv0; sf[nt][1] += fmv1;
                    sf[nt][2] += fmv0; sf[nt][3] += fmv1;
                }
            }
#pragma unroll
            for (int nt = 0; nt < 8; nt++) {
                sf[nt][0] = __expf(sf[nt][0]);
                sf[nt][1] = __expf(sf[nt][1]);
                sf[nt][2] = __expf(sf[nt][2]);
                sf[nt][3] = __expf(sf[nt][3]);
                l_[0] += sf[nt][0] + sf[nt][1];
                l_[1] += sf[nt][2] + sf[nt][3];
            }

            // ---- P fragments (fp16) ----
            uint32_t pf[4][4];
#pragma unroll
            for (int kc = 0; kc < 4; kc++) {
                pf[kc][0] = packh2(sf[2 * kc][0],     sf[2 * kc][1]);
                pf[kc][1] = packh2(sf[2 * kc][2],     sf[2 * kc][3]);
                pf[kc][2] = packh2(sf[2 * kc + 1][0], sf[2 * kc + 1][1]);
                pf[kc][3] = packh2(sf[2 * kc + 1][2], sf[2 * kc + 1][3]);
            }

            // ---- O += P V ----
#pragma unroll
            for (int kc = 0; kc < 4; kc++) {
                uint32_t vfr[4][4];
#pragma unroll
                for (int nn = 0; nn < 4; nn++)
                    ldsm4(vfr[nn], Vb + SWZ((nn * 16 + lrow) * 128 + kc * 32 + lsel));
#pragma unroll
                for (int dt = 0; dt < 8; dt++)
                    mma16816h(o[dt], pf[kc],
                              vfr[dt >> 1][dt & 1], vfr[dt >> 1][(dt & 1) + 2]);
            }
        }

        __syncthreads();
        if (t + 2 <= ke) att_issue(sb, s, t + 2, q0, bh, tid);
        CP_COMMIT();
    }

    // ---- single l reduction after the loop ----
    l_[0] += __shfl_xor_sync(0xffffffffu, l_[0], 1);
    l_[0] += __shfl_xor_sync(0xffffffffu, l_[0], 2);
    l_[1] += __shfl_xor_sync(0xffffffffu, l_[1], 1);
    l_[1] += __shfl_xor_sync(0xffffffffu, l_[1], 2);

    // ---- normalize + store ----
    const float inv0 = 1.f / l_[0];
    const float inv1 = 1.f / l_[1];
    const size_t base0 = ((size_t)b * SS + row0) * EE + h * 64;
    const size_t base1 = base0 + (size_t)8 * EE;
#pragma unroll
    for (int dt = 0; dt < 8; dt++) {
        const int d = dt * 8 + colb;
        float2 w0 = make_float2(o[dt][0] * inv0, o[dt][1] * inv0);
        float2 w1 = make_float2(o[dt][2] * inv1, o[dt][3] * inv1);
        *(float2*)&out[base0 + d] = w0;
        *(float2*)&out[base1 + d] = w1;
    }
}

// ---------------------------------------------------------------------------
extern "C" void kernel_launch(void* const* d_in, const int* in_sizes, int n_in,
                              void* d_out, int out_size) {
    const float* hs  = (const float*)d_in[0];
    const int*   am  = (const int*)d_in[1];
    const float* q_w = (const float*)d_in[2];
    const float* q_b = (const float*)d_in[3];
    const float* k_w = (const float*)d_in[4];
    const float* k_b = (const float*)d_in[5];
    const float* v_w = (const float*)d_in[6];
    const float* v_b = (const float*)d_in[7];
    float* out = (float*)d_out;

    cudaFuncSetAttribute(qkv_hmma_gemm, cudaFuncAttributeMaxDynamicSharedMemorySize,
                         GEMM_SMEM);
    cudaFuncSetAttribute(attn_hmma, cudaFuncAttributeMaxDynamicSharedMemorySize,
                         ATT_SMEM);

    conv_all<<<(XELEM + 3 * EE * EE) / 1024, 256>>>(hs, q_w, k_w, v_w);

    dim3 g(NTOT / 128, (BB * SS) / 128);   // (24, 64)
    qkv_hmma_gemm<<<g, 128, GEMM_SMEM>>>(q_b, k_b, v_b);

    attn_hmma<<<BB * HH * (SS / 128), 256, ATT_SMEM>>>(am, out);
}